// round 4
// baseline (speedup 1.0000x reference)
#include <cuda_runtime.h>
#include <cfloat>
#include <cstdint>

// xp: (32, 64, 64, 512) fp32, m innermost. out: (32, 48*512), bin = iw*6+ih.
// Resize is identity. Row bins: 8 rows each. Col edges: {0,11,21,32,43,53,64}.
//
// R4 (ceiling test): replace the per-thread LDG stream with cp.async.bulk
// (TMA-1D) segment copies into a double-buffered smem ring. Each bin row is a
// contiguous 20/22KB gmem segment; one elected thread issues bulk copies with
// mbarrier complete_tx; 128 threads max-reduce each segment from smem.
// This removes the L1tex/LSU per-warp path entirely and drives DRAM with
// large linear bursts from the async proxy.

#define B_DIM 32
#define W_DIM 64
#define H_DIM 64
#define M_DIM 512
#define W_BINS 8
#define H_BINS 6
#define M4 128                    // float4 per (b,r,c)
#define ROWF (H_DIM * M_DIM)      // floats per image row (64 cols * 512) = 32768
#define SEG_MAX_BYTES (11 * 2048) // widest bin row: 11 cols * 2KB

__constant__ int C_EDGE[H_BINS + 1] = {0, 11, 21, 32, 43, 53, 64};

static __device__ __forceinline__ float4 fmax4(float4 a, float4 b) {
    a.x = fmaxf(a.x, b.x);
    a.y = fmaxf(a.y, b.y);
    a.z = fmaxf(a.z, b.z);
    a.w = fmaxf(a.w, b.w);
    return a;
}

static __device__ __forceinline__ uint32_t s2u(const void* p) {
    uint32_t a;
    asm("{ .reg .u64 t; cvta.to.shared.u64 t, %1; cvt.u32.u64 %0, t; }"
        : "=r"(a) : "l"(p));
    return a;
}

static __device__ __forceinline__ void mbar_init(uint32_t m, uint32_t cnt) {
    asm volatile("mbarrier.init.shared.b64 [%0], %1;" :: "r"(m), "r"(cnt) : "memory");
}
static __device__ __forceinline__ void mbar_arrive(uint32_t m) {
    asm volatile("mbarrier.arrive.shared.b64 _, [%0];" :: "r"(m) : "memory");
}
static __device__ __forceinline__ void mbar_expect_tx(uint32_t m, uint32_t bytes) {
    asm volatile("mbarrier.arrive.expect_tx.shared.b64 _, [%0], %1;"
                 :: "r"(m), "r"(bytes) : "memory");
}
static __device__ __forceinline__ void mbar_wait(uint32_t m, uint32_t parity) {
    uint32_t done;
    asm volatile(
        "{\n\t.reg .pred p;\n\t"
        "mbarrier.try_wait.parity.acquire.cta.shared::cta.b64 p, [%1], %2;\n\t"
        "selp.b32 %0, 1, 0, p;\n\t}"
        : "=r"(done) : "r"(m), "r"(parity) : "memory");
    while (!done) {
        asm volatile(
            "{\n\t.reg .pred p;\n\t"
            "mbarrier.try_wait.parity.acquire.cta.shared::cta.b64 p, [%1], %2, 0x989680;\n\t"
            "selp.b32 %0, 1, 0, p;\n\t}"
            : "=r"(done) : "r"(m), "r"(parity) : "memory");
    }
}
static __device__ __forceinline__ void bulk_g2s(uint32_t dst, const void* src,
                                                uint32_t bytes, uint32_t mbar) {
    asm volatile(
        "cp.async.bulk.shared::cluster.global.mbarrier::complete_tx::bytes "
        "[%0], [%1], %2, [%3];"
        :: "r"(dst), "l"(src), "r"(bytes), "r"(mbar) : "memory");
}

__global__ __launch_bounds__(M4)
void adaptive_maxpool_tma_kernel(const float* __restrict__ x,
                                 float4* __restrict__ out4) {
    __shared__ alignas(128) unsigned char buf[2][SEG_MAX_BYTES];
    __shared__ uint64_t mb_full[2], mb_empty[2];

    const int bin = blockIdx.x;       // 0..47  (iw*6 + ih)
    const int b   = blockIdx.y;       // 0..31
    const int iw  = bin / H_BINS;
    const int ih  = bin - iw * H_BINS;

    const int r1 = iw * (W_DIM / W_BINS);       // 8 rows per bin
    const int c1 = C_EDGE[ih];
    const int nc = C_EDGE[ih + 1] - c1;         // 10 or 11
    const uint32_t seg_bytes = (uint32_t)nc * (M_DIM * 4);  // 20480 or 22528

    const int t = threadIdx.x;                  // 0..127
    const float* src0 = x + ((size_t)(b * W_DIM + r1) * H_DIM + c1) * M_DIM;

    const uint32_t full_a[2]  = { s2u(&mb_full[0]),  s2u(&mb_full[1])  };
    const uint32_t empty_a[2] = { s2u(&mb_empty[0]), s2u(&mb_empty[1]) };
    const float4* bufp[2] = { (const float4*)buf[0], (const float4*)buf[1] };
    const uint32_t bufa[2] = { s2u(buf[0]), s2u(buf[1]) };

    if (t == 0) {
        mbar_init(full_a[0], 1);
        mbar_init(full_a[1], 1);
        mbar_init(empty_a[0], M4);
        mbar_init(empty_a[1], M4);
    }
    __syncthreads();

    // Prologue: fill both stages (segments 0 and 1).
    if (t == 0) {
        mbar_expect_tx(full_a[0], seg_bytes);
        bulk_g2s(bufa[0], src0 + 0 * (size_t)ROWF, seg_bytes, full_a[0]);
        mbar_expect_tx(full_a[1], seg_bytes);
        bulk_g2s(bufa[1], src0 + 1 * (size_t)ROWF, seg_bytes, full_a[1]);
    }

    float4 acc = make_float4(-FLT_MAX, -FLT_MAX, -FLT_MAX, -FLT_MAX);
    int pf[2] = {0, 0};   // consumer full-parity per stage
    int pe[2] = {0, 0};   // producer empty-parity per stage

    #pragma unroll 1
    for (int s = 0; s < 8; ++s) {
        const int st = s & 1;

        // Wait for segment s data.
        mbar_wait(full_a[st], pf[st]);
        pf[st] ^= 1;

        // Reduce segment (nc * 128 float4, thread t owns lane t of each col).
        const float4* bp = bufp[st];
        #pragma unroll 1
        for (int c = 0; c < nc; ++c) {
            acc = fmax4(acc, bp[c * M4 + t]);
        }

        // Free the stage.
        mbar_arrive(empty_a[st]);

        // Producer: refill this stage with segment s+2.
        if (t == 0 && s + 2 < 8) {
            mbar_wait(empty_a[st], pe[st]);
            pe[st] ^= 1;
            mbar_expect_tx(full_a[st], seg_bytes);
            bulk_g2s(bufa[st], src0 + (size_t)(s + 2) * ROWF, seg_bytes, full_a[st]);
        }
    }

    out4[((size_t)b * (W_BINS * H_BINS) + bin) * M4 + t] = acc;
}

extern "C" void kernel_launch(void* const* d_in, const int* in_sizes, int n_in,
                              void* d_out, int out_size) {
    (void)in_sizes; (void)n_in; (void)out_size;
    const float* x = (const float*)d_in[0];
    float4* o4 = (float4*)d_out;

    dim3 grid(W_BINS * H_BINS, B_DIM);   // (48, 32) = 1536 blocks
    adaptive_maxpool_tma_kernel<<<grid, M4>>>(x, o4);
}

// round 5
// speedup vs baseline: 1.2023x; 1.2023x over previous
#include <cuda_runtime.h>
#include <cfloat>

// xp: (32, 64, 64, 512) fp32, m innermost. out: (32, 48*512), bin = iw*6+ih.
// Resize is identity. Row bins: 8 rows each. Col edges: {0,11,21,32,43,53,64}.
//
// R5 (DRAM page-locality test): instead of one block per (b, bin) hopping
// between 20-22KB column slivers (~2400 short streams chip-wide, DRAM pinned
// at 78%), one block per (b, iw) superblock streams its CONTIGUOUS 1MB region
// linearly (4 rquads x 2 rows = 4 parallel 256KB streams), bucketing columns
// into 6 accumulators with compile-time bin selection. Cross-rquad combine in
// smem. Long linear streams -> higher DRAM row-buffer hit rate.

#define B_DIM 32
#define W_DIM 64
#define H_DIM 64
#define M_DIM 512
#define W_BINS 8
#define H_BINS 6
#define M4 (M_DIM / 4)            // 128 float4 lanes per (b,r,c)
#define ROW4 (H_DIM * M4)         // float4 per image row = 8192

// Column bin for col c: edges {0,11,21,32,43,53,64} (compile-time).
#define BIN_OF(c) ((c) < 11 ? 0 : (c) < 21 ? 1 : (c) < 32 ? 2 : \
                   (c) < 43 ? 3 : (c) < 53 ? 4 : 5)

static __device__ __forceinline__ float4 fmax4(float4 a, float4 b) {
    a.x = fmaxf(a.x, b.x);
    a.y = fmaxf(a.y, b.y);
    a.z = fmaxf(a.z, b.z);
    a.w = fmaxf(a.w, b.w);
    return a;
}

// Block = (iw, b): 512 threads = 128 channel-lanes x 4 row-quads.
// rquad q streams rows [iw*8 + 2q, iw*8 + 2q + 2): 256KB contiguous.
__global__ __launch_bounds__(512, 1)
void adaptive_maxpool_stream_kernel(const float4* __restrict__ x4,
                                    float4* __restrict__ out4) {
    const int iw = blockIdx.x;        // 0..7
    const int b  = blockIdx.y;        // 0..31

    const int t    = threadIdx.x;     // 0..511
    const int lane = t & (M4 - 1);    // 0..127 (channel float4)
    const int rq   = t >> 7;          // 0..3

    const int r0 = iw * 8 + rq * 2;   // first of this thread's 2 rows
    const float4* base =
        x4 + ((size_t)(b * W_DIM + r0)) * ROW4 + lane;

    float4 acc[H_BINS];
    #pragma unroll
    for (int k = 0; k < H_BINS; ++k)
        acc[k] = make_float4(-FLT_MAX, -FLT_MAX, -FLT_MAX, -FLT_MAX);

    // Linear sweep of 2 full rows; bin chosen at compile time per column.
    #pragma unroll
    for (int r = 0; r < 2; ++r) {
        const float4* row = base + (size_t)r * ROW4;
        #pragma unroll
        for (int c = 0; c < H_DIM; ++c) {
            acc[BIN_OF(c)] = fmax4(acc[BIN_OF(c)], __ldcs(row + (size_t)c * M4));
        }
    }

    // Combine the 4 rquads: rquads 1..3 publish, rquad 0 reduces + stores.
    __shared__ float4 sh[3][H_BINS][M4];   // 36 KB

    if (rq > 0) {
        #pragma unroll
        for (int k = 0; k < H_BINS; ++k)
            sh[rq - 1][k][lane] = acc[k];
    }
    __syncthreads();

    if (rq == 0) {
        #pragma unroll
        for (int k = 0; k < H_BINS; ++k) {
            float4 v = acc[k];
            v = fmax4(v, sh[0][k][lane]);
            v = fmax4(v, sh[1][k][lane]);
            v = fmax4(v, sh[2][k][lane]);
            out4[((size_t)(b * (W_BINS * H_BINS)) + iw * H_BINS + k) * M4 + lane] = v;
        }
    }
}

extern "C" void kernel_launch(void* const* d_in, const int* in_sizes, int n_in,
                              void* d_out, int out_size) {
    (void)in_sizes; (void)n_in; (void)out_size;
    const float4* x4 = (const float4*)d_in[0];
    float4* o4 = (float4*)d_out;

    dim3 grid(W_BINS, B_DIM);   // (8, 32) = 256 blocks
    adaptive_maxpool_stream_kernel<<<grid, 512>>>(x4, o4);
}